// round 9
// baseline (speedup 1.0000x reference)
#include <cuda_runtime.h>
#include <math.h>

#define SEQ   2048
#define NH    32
#define HD    64
#define HIDD  2048
#define NB    2
#define NQKV  (3 * NH * HD)   // 6144
#define MROWS (NB * SEQ)      // 4096

// Scratch (static __device__ arrays per harness rules — no cudaMalloc anywhere)
__device__ float g_qkv[(size_t)MROWS * NQKV];          // [4096][6144] raw QKV
__device__ float g_Q[(size_t)NB * NH * SEQ * HD];      // [B,H,S,D], pre-scaled by 1/8
__device__ float g_K[(size_t)NB * NH * SEQ * HD];
__device__ float g_V[(size_t)NB * NH * SEQ * HD];
__device__ float g_attn[(size_t)MROWS * HIDD];         // [4096][2048]
__device__ int   g_mask_u8;                            // 1 = 1-byte bool, 0 = 4-byte words

// ---------------------------------------------------------------------------
// Detect the attention_mask element width. Bool serialized as 1-byte has 0x01
// bytes at intra-word positions >= 1 (random 0/1 bytes). int32 "1" is
// 01 00 00 00 and float32 "1.0" is 00 00 80 3F — neither ever has 0x01 at
// byte positions 1..3. Scan 1 MB (well within the smallest possible buffer).
// ---------------------------------------------------------------------------
__global__ void detect_mask_kernel(const unsigned char* __restrict__ m) {
    __shared__ int found;
    if (threadIdx.x == 0) found = 0;
    __syncthreads();
    const uint4* p = (const uint4*)m;
    int f = 0;
    for (int i = threadIdx.x; i < 65536; i += blockDim.x) {
        uint4 w = p[i];
        unsigned ws[4] = {w.x, w.y, w.z, w.w};
#pragma unroll
        for (int j = 0; j < 4; ++j) {
            unsigned v = ws[j];
            if (((v >> 8) & 0xFFu) == 1u || ((v >> 16) & 0xFFu) == 1u ||
                ((v >> 24) & 0xFFu) == 1u)
                f = 1;
        }
    }
    if (f) atomicOr(&found, 1);
    __syncthreads();
    if (threadIdx.x == 0) g_mask_u8 = found;
}

// ---------------------------------------------------------------------------
// C[m][n] = sum_k A[m][k] * B[n][k]   (NT GEMM, both operands K-major)
// 128x128 block tile, BK=8, 256 threads, 8x8 per-thread register tile.
// ---------------------------------------------------------------------------
__global__ __launch_bounds__(256, 2) void sgemm_nt(const float* __restrict__ A,
                                                   const float* __restrict__ B,
                                                   float* __restrict__ C,
                                                   int K, int N) {
    __shared__ float As[8][128];
    __shared__ float Bs[8][128];
    const int tid = threadIdx.x;
    const int m0 = blockIdx.y * 128;
    const int n0 = blockIdx.x * 128;
    const int lr = tid >> 1;
    const int lc = (tid & 1) << 2;
    const float* Ag = A + (size_t)(m0 + lr) * K + lc;
    const float* Bg = B + (size_t)(n0 + lr) * K + lc;
    const int ty = tid >> 4;
    const int tx = tid & 15;

    float acc[8][8];
#pragma unroll
    for (int i = 0; i < 8; ++i)
#pragma unroll
        for (int j = 0; j < 8; ++j) acc[i][j] = 0.f;

    for (int k0 = 0; k0 < K; k0 += 8) {
        float4 av = *(const float4*)(Ag + k0);
        float4 bv = *(const float4*)(Bg + k0);
        __syncthreads();
        As[lc + 0][lr] = av.x; As[lc + 1][lr] = av.y;
        As[lc + 2][lr] = av.z; As[lc + 3][lr] = av.w;
        Bs[lc + 0][lr] = bv.x; Bs[lc + 1][lr] = bv.y;
        Bs[lc + 2][lr] = bv.z; Bs[lc + 3][lr] = bv.w;
        __syncthreads();
#pragma unroll
        for (int kk = 0; kk < 8; ++kk) {
            float4 a0 = *(const float4*)&As[kk][ty << 2];
            float4 a1 = *(const float4*)&As[kk][64 + (ty << 2)];
            float4 b0 = *(const float4*)&Bs[kk][tx << 2];
            float4 b1 = *(const float4*)&Bs[kk][64 + (tx << 2)];
            float a[8] = {a0.x, a0.y, a0.z, a0.w, a1.x, a1.y, a1.z, a1.w};
            float bb[8] = {b0.x, b0.y, b0.z, b0.w, b1.x, b1.y, b1.z, b1.w};
#pragma unroll
            for (int i = 0; i < 8; ++i)
#pragma unroll
                for (int j = 0; j < 8; ++j)
                    acc[i][j] = fmaf(a[i], bb[j], acc[i][j]);
        }
    }
#pragma unroll
    for (int i = 0; i < 8; ++i) {
        int m = m0 + ((i < 4) ? (ty * 4 + i) : (64 + ty * 4 + i - 4));
        float4 c0 = make_float4(acc[i][0], acc[i][1], acc[i][2], acc[i][3]);
        float4 c1 = make_float4(acc[i][4], acc[i][5], acc[i][6], acc[i][7]);
        *(float4*)(C + (size_t)m * N + n0 + (tx << 2)) = c0;
        *(float4*)(C + (size_t)m * N + n0 + 64 + (tx << 2)) = c1;
    }
}

// ---------------------------------------------------------------------------
// Split raw QKV into Q/K/V [B,H,S,D]; apply RoPE to Q,K; fold 1/sqrt(D) into Q.
// Angle rounded to f32 exactly like the reference table (f32 pos * f32 invfreq),
// then sin/cos in double of that f32 angle for accuracy.
// ---------------------------------------------------------------------------
__global__ __launch_bounds__(256) void rope_scatter(const float* __restrict__ qkv,
                                                    const int* __restrict__ pos_ids) {
    int idx = blockIdx.x * blockDim.x + threadIdx.x;   // NB*SEQ*NH*32 threads
    int d = idx & 31;
    int h = (idx >> 5) & (NH - 1);
    int s = (idx >> 10) & (SEQ - 1);
    int b = idx >> 21;
    int pos = pos_ids[b * SEQ + s];

    const float* src = qkv + (size_t)(b * SEQ + s) * NQKV + h * (3 * HD);
    float q1 = src[d],       q2 = src[d + 32];
    float k1 = src[64 + d],  k2 = src[96 + d];
    float v1 = src[128 + d], v2 = src[160 + d];

    float invf = (float)pow(10000.0, -(double)d / 32.0);
    float t = (float)pos * invf;
    float sn = (float)sin((double)t);
    float cs = (float)cos((double)t);

    size_t dst = ((size_t)(b * NH + h) * SEQ + s) * HD;
    const float qs = 0.125f;   // 1/sqrt(64)
    g_Q[dst + d]      = (q1 * cs - q2 * sn) * qs;
    g_Q[dst + d + 32] = (q2 * cs + q1 * sn) * qs;
    g_K[dst + d]      = k1 * cs - k2 * sn;
    g_K[dst + d + 32] = k2 * cs + k1 * sn;
    g_V[dst + d]      = v1;
    g_V[dst + d + 32] = v2;
}

// ---------------------------------------------------------------------------
// Flash attention, fp32. One block per (b, h, 64-row q tile). 256 threads.
// S-tile 64x64 with 4x4 per-thread register tiles; online softmax; P in smem.
// Mask element width selected at runtime via g_mask_u8.
// ---------------------------------------------------------------------------
__global__ __launch_bounds__(256) void flash_attn(const unsigned char* __restrict__ mask,
                                                  float* __restrict__ attn) {
    extern __shared__ float sm[];
    float* Qt  = sm;               // [64 d][64 q]
    float* Kt  = Qt + 64 * 64;     // [64 d][64 k]
    float* Vs  = Kt + 64 * 64;     // [64 k][64 d]
    float* Ps  = Vs + 64 * 64;     // [64 q][64 k]
    float* red = Ps + 64 * 64;     // [64 q][16 tx]
    float* m_s = red + 64 * 16;    // running row max [64]
    float* l_s = m_s + 64;         // running row sum [64]
    float* c_s = l_s + 64;         // per-tile correction [64]

    const int q0 = blockIdx.x * 64;
    const int h  = blockIdx.y;
    const int b  = blockIdx.z;
    const int tid = threadIdx.x;
    const int ty = tid >> 4, tx = tid & 15;
    const size_t head_base = (size_t)(b * NH + h) * SEQ;
    const int mask_u8 = g_mask_u8;

    // Load Q tile (transposed to d-major)
    {
        int q = tid >> 2, d0 = (tid & 3) << 4;
        const float* src = g_Q + (head_base + q0 + q) * HD + d0;
#pragma unroll
        for (int j = 0; j < 16; ++j) Qt[(d0 + j) * 64 + q] = src[j];
    }
    if (tid < 64) { m_s[tid] = -INFINITY; l_s[tid] = 0.f; }

    float o[4][4];
#pragma unroll
    for (int i = 0; i < 4; ++i)
#pragma unroll
        for (int j = 0; j < 4; ++j) o[i][j] = 0.f;

    for (int k0 = 0; k0 < SEQ; k0 += 64) {
        __syncthreads();   // protect Kt/Vs/Ps reuse vs previous iteration
        {
            int r = tid >> 2, d0 = (tid & 3) << 4;
            const float* ks = g_K + (head_base + k0 + r) * HD + d0;
            const float* vs = g_V + (head_base + k0 + r) * HD + d0;
#pragma unroll
            for (int j = 0; j < 16; ++j) Kt[(d0 + j) * 64 + r] = ks[j];
#pragma unroll
            for (int j = 0; j < 16; ++j) Vs[r * 64 + d0 + j] = vs[j];
        }
        __syncthreads();

        // S = Q K^T (Q already scaled by 1/8)
        float s[4][4];
#pragma unroll
        for (int i = 0; i < 4; ++i)
#pragma unroll
            for (int j = 0; j < 4; ++j) s[i][j] = 0.f;
#pragma unroll 8
        for (int kk = 0; kk < 64; ++kk) {
            float a0 = Qt[kk * 64 + ty * 4 + 0];
            float a1 = Qt[kk * 64 + ty * 4 + 1];
            float a2 = Qt[kk * 64 + ty * 4 + 2];
            float a3 = Qt[kk * 64 + ty * 4 + 3];
            float4 bq = *(const float4*)&Kt[kk * 64 + (tx << 2)];
            s[0][0] = fmaf(a0, bq.x, s[0][0]); s[0][1] = fmaf(a0, bq.y, s[0][1]);
            s[0][2] = fmaf(a0, bq.z, s[0][2]); s[0][3] = fmaf(a0, bq.w, s[0][3]);
            s[1][0] = fmaf(a1, bq.x, s[1][0]); s[1][1] = fmaf(a1, bq.y, s[1][1]);
            s[1][2] = fmaf(a1, bq.z, s[1][2]); s[1][3] = fmaf(a1, bq.w, s[1][3]);
            s[2][0] = fmaf(a2, bq.x, s[2][0]); s[2][1] = fmaf(a2, bq.y, s[2][1]);
            s[2][2] = fmaf(a2, bq.z, s[2][2]); s[2][3] = fmaf(a2, bq.w, s[2][3]);
            s[3][0] = fmaf(a3, bq.x, s[3][0]); s[3][1] = fmaf(a3, bq.y, s[3][1]);
            s[3][2] = fmaf(a3, bq.z, s[3][2]); s[3][3] = fmaf(a3, bq.w, s[3][3]);
        }

        // Mask: where(mask) -> -10000 (replace). Element index:
        // e = (b*S + q)*S + k, 4 consecutive k per thread, e % 4 == 0.
#pragma unroll
        for (int i = 0; i < 4; ++i) {
            size_t e = ((size_t)b * SEQ + q0 + ty * 4 + i) * SEQ + k0 + (tx << 2);
            if (mask_u8) {
                unsigned mm = *(const unsigned*)(mask + e);
                if (mm & 0x000000FFu) s[i][0] = -10000.f;
                if (mm & 0x0000FF00u) s[i][1] = -10000.f;
                if (mm & 0x00FF0000u) s[i][2] = -10000.f;
                if (mm & 0xFF000000u) s[i][3] = -10000.f;
            } else {
                uint4 w = *(const uint4*)((const unsigned*)mask + e);
                if (w.x) s[i][0] = -10000.f;
                if (w.y) s[i][1] = -10000.f;
                if (w.z) s[i][2] = -10000.f;
                if (w.w) s[i][3] = -10000.f;
            }
        }

        // Row max (per-thread then cross-tx via smem)
#pragma unroll
        for (int i = 0; i < 4; ++i) {
            float rm = fmaxf(fmaxf(s[i][0], s[i][1]), fmaxf(s[i][2], s[i][3]));
            red[(ty * 4 + i) * 16 + tx] = rm;
        }
        __syncthreads();
        if (tid < 64) {
            float mt = red[tid * 16];
#pragma unroll
            for (int j = 1; j < 16; ++j) mt = fmaxf(mt, red[tid * 16 + j]);
            float mo = m_s[tid];
            float mn = fmaxf(mo, mt);
            m_s[tid] = mn;
            c_s[tid] = expf(mo - mn);   // expf(-inf)=0 on first tile
        }
        __syncthreads();

        // P = exp(S - m_new), row sums, store P to smem
#pragma unroll
        for (int i = 0; i < 4; ++i) {
            float mn = m_s[ty * 4 + i];
            float rs = 0.f;
#pragma unroll
            for (int j = 0; j < 4; ++j) {
                float p = expf(s[i][j] - mn);
                rs += p;
                Ps[(ty * 4 + i) * 64 + (tx << 2) + j] = p;
            }
            red[(ty * 4 + i) * 16 + tx] = rs;
        }
        __syncthreads();
        if (tid < 64) {
            float rs = 0.f;
#pragma unroll
            for (int j = 0; j < 16; ++j) rs += red[tid * 16 + j];
            l_s[tid] = l_s[tid] * c_s[tid] + rs;
        }

        // Rescale O, then O += P V
        float cc[4];
#pragma unroll
        for (int i = 0; i < 4; ++i) cc[i] = c_s[ty * 4 + i];
#pragma unroll
        for (int i = 0; i < 4; ++i)
#pragma unroll
            for (int j = 0; j < 4; ++j) o[i][j] *= cc[i];
#pragma unroll 8
        for (int kk = 0; kk < 64; ++kk) {
            float a0 = Ps[(ty * 4 + 0) * 64 + kk];
            float a1 = Ps[(ty * 4 + 1) * 64 + kk];
            float a2 = Ps[(ty * 4 + 2) * 64 + kk];
            float a3 = Ps[(ty * 4 + 3) * 64 + kk];
            float4 v = *(const float4*)&Vs[kk * 64 + (tx << 2)];
            o[0][0] = fmaf(a0, v.x, o[0][0]); o[0][1] = fmaf(a0, v.y, o[0][1]);
            o[0][2] = fmaf(a0, v.z, o[0][2]); o[0][3] = fmaf(a0, v.w, o[0][3]);
            o[1][0] = fmaf(a1, v.x, o[1][0]); o[1][1] = fmaf(a1, v.y, o[1][1]);
            o[1][2] = fmaf(a1, v.z, o[1][2]); o[1][3] = fmaf(a1, v.w, o[1][3]);
            o[2][0] = fmaf(a2, v.x, o[2][0]); o[2][1] = fmaf(a2, v.y, o[2][1]);
            o[2][2] = fmaf(a2, v.z, o[2][2]); o[2][3] = fmaf(a2, v.w, o[2][3]);
            o[3][0] = fmaf(a3, v.x, o[3][0]); o[3][1] = fmaf(a3, v.y, o[3][1]);
            o[3][2] = fmaf(a3, v.z, o[3][2]); o[3][3] = fmaf(a3, v.w, o[3][3]);
        }
    }
    __syncthreads();   // l_s final

    float inv[4];
#pragma unroll
    for (int i = 0; i < 4; ++i) inv[i] = 1.f / l_s[ty * 4 + i];
#pragma unroll
    for (int i = 0; i < 4; ++i) {
        float4 r = make_float4(o[i][0] * inv[i], o[i][1] * inv[i],
                               o[i][2] * inv[i], o[i][3] * inv[i]);
        *(float4*)(attn + ((size_t)b * SEQ + q0 + ty * 4 + i) * HIDD +
                   h * HD + (tx << 2)) = r;
    }
}

// ---------------------------------------------------------------------------
extern "C" void kernel_launch(void* const* d_in, const int* in_sizes, int n_in,
                              void* d_out, int out_size) {
    (void)in_sizes; (void)n_in; (void)out_size;
    const float* hidden        = (const float*)d_in[0];
    const unsigned char* mask  = (const unsigned char*)d_in[1];
    const int* pos             = (const int*)d_in[2];
    const float* Wqkv          = (const float*)d_in[3];
    const float* Wo            = (const float*)d_in[4];
    float* out                 = (float*)d_out;

    float* qkv = nullptr;
    float* attn = nullptr;
    cudaGetSymbolAddress((void**)&qkv, g_qkv);
    cudaGetSymbolAddress((void**)&attn, g_attn);

    const int smem_bytes = (4 * 64 * 64 + 64 * 16 + 3 * 64) * (int)sizeof(float); // 70400
    cudaFuncSetAttribute(flash_attn, cudaFuncAttributeMaxDynamicSharedMemorySize,
                         smem_bytes);

    detect_mask_kernel<<<1, 256>>>(mask);

    dim3 gqkv(NQKV / 128, MROWS / 128);        // 48 x 32
    sgemm_nt<<<gqkv, 256>>>(hidden, Wqkv, qkv, HIDD, NQKV);

    rope_scatter<<<(NB * SEQ * NH * 32) / 256, 256>>>(qkv, pos);

    dim3 gatt(SEQ / 64, NH, NB);               // 32 x 32 x 2
    flash_attn<<<gatt, 256, smem_bytes>>>(mask, attn);

    dim3 go(HIDD / 128, MROWS / 128);          // 16 x 32
    sgemm_nt<<<go, 256>>>(attn, Wo, out, HIDD, HIDD);
}